// round 15
// baseline (speedup 1.0000x reference)
#include <cuda_runtime.h>

#define K1v 16
#define BATCH 16
#define CH 32
#define NP 4096
#define EDG (NP*K1v)          // 65536
#define TP 16                 // points per CTA
#define RR 256                // rows per CTA
#define INVC 0.9999950000374997f  // 1/sqrt(1+1e-5)

typedef unsigned long long u64;

// Scratch (no cudaMalloc allowed)
__device__ int   g_idx[BATCH*NP*K1v];                  // 4 MB
__device__ __align__(16) float g_featT[BATCH*NP*CH];   // 8 MB (B,P,C)
__device__ int   g_brk[BATCH*256];
__device__ __align__(16) u64   g_wD[4096];       // dup'd (w,w): [c][128o] = ss0*W0h | ss0*W0l | ssc*SW
__device__ __align__(16) float g_w1T[1024];      // (g1*INVC)*W1   [k][32o]
__device__ __align__(16) float g_w2T[2048];      // (g2*INVC/16)*W2 [k][64o]
__device__ __align__(16) float gY0[BATCH*NP*32]; // ss0*(W0h f)   8 MB
__device__ __align__(16) float gA [BATCH*NP*32]; // pb0 - Y0s     8 MB
__device__ __align__(16) float gSC[BATCH*NP*64]; // shortcut     16 MB

__device__ __forceinline__ u64 fma2(u64 a, u64 b, u64 c) {
    u64 d;
    asm("fma.rn.f32x2 %0, %1, %2, %3;" : "=l"(d) : "l"(a), "l"(b), "l"(c));
    return d;
}
__device__ __forceinline__ u64 add2(u64 a, u64 b) {
    u64 d;
    asm("add.rn.f32x2 %0, %1, %2;" : "=l"(d) : "l"(a), "l"(b));
    return d;
}
__device__ __forceinline__ u64 pack2(float x, float y) {
    u64 d;
    asm("mov.b64 %0, {%1, %2};" : "=l"(d) : "f"(x), "f"(y));
    return d;
}
__device__ __forceinline__ void unpack2(u64 v, float& x, float& y) {
    asm("mov.b64 {%0, %1}, %2;" : "=f"(x), "=f"(y) : "l"(v));
}

// ---------------------------------------------------------------------------
// Weight prep: g_wD dup'd [c][128] (scales folded); w1T/w2T [k][o] scale-folded.
// ---------------------------------------------------------------------------
__global__ void wprep_kernel(const float* __restrict__ W0, const float* __restrict__ W1,
                             const float* __restrict__ W2, const float* __restrict__ SW,
                             const float* __restrict__ g0, const float* __restrict__ sg,
                             const float* __restrict__ g1, const float* __restrict__ g2) {
    int t = blockIdx.x * 256 + threadIdx.x;   // 0..7167
    if (t < 4096) {
        int c = t >> 7, j = t & 127;
        float v;
        if (j < 32)       v = g0[j] * INVC * W0[j * 64 + 32 + c];
        else if (j < 64)  { int o = j - 32; v = g0[o] * INVC * W0[o * 64 + c]; }
        else              { int o = j - 64; v = sg[o] * INVC * SW[o * 32 + c]; }
        g_wD[t] = pack2(v, v);
    } else if (t < 5120) {
        int i = t - 4096, k = i >> 5, o = i & 31;
        g_w1T[k * 32 + o] = g1[o] * INVC * W1[o * 32 + k];
    } else if (t < 7168) {
        int i = t - 5120, k = i >> 6, o = i & 63;
        g_w2T[k * 64 + o] = g2[o] * (INVC / 16.0f) * W2[o * 32 + k];
    }
}

// ---------------------------------------------------------------------------
// Edge preprocessing: prep (defaults + per-chunk break) -> scatter
// ---------------------------------------------------------------------------
__global__ void prep_kernel(const int* __restrict__ ef) {
    const int blk   = blockIdx.x;
    const int b     = blk >> 8;
    const int chunk = blk & 255;
    const int t     = threadIdx.x;
    const int e     = chunk * 256 + t;

    g_idx[(b << 16) | e] = NP - K1v + (e & 15);

    const int* __restrict__ pf = ef + (size_t)b * 2 * EDG;
    int brk = EDG;
    if (e > 0 && pf[e] == 0 && pf[e - 1] != 0) brk = e;

    __shared__ int s[256];
    s[t] = brk;
    __syncthreads();
    #pragma unroll
    for (int off = 128; off > 0; off >>= 1) {
        if (t < off) s[t] = min(s[t], s[t + off]);
        __syncthreads();
    }
    if (t == 0) g_brk[b * 256 + chunk] = s[0];
}

__global__ void scatter_kernel(const int* __restrict__ ef) {
    const int b  = blockIdx.y;
    const int e0 = blockIdx.x * 256;
    const int t  = threadIdx.x;
    const int e  = e0 + t;
    const int* __restrict__ pf = ef + (size_t)b * 2 * EDG;
    const int* __restrict__ tg = pf + EDG;

    __shared__ int s[272];
    __shared__ int sm2[256];
    sm2[t] = g_brk[b * 256 + t];
    for (int i = t; i < 272; i += 256) {
        int src = e0 - 16 + i;
        s[i] = (src >= 0) ? pf[src] : -1;
    }
    __syncthreads();
    #pragma unroll
    for (int off = 128; off > 0; off >>= 1) {
        if (t < off) sm2[t] = min(sm2[t], sm2[t + off]);
        __syncthreads();
    }
    const int broken = sm2[0];

    int v = s[t + 16];
    int j = 0, m = e, si = t + 16;
    while (m > 0 && j < 16 && s[si - 1] == v) { m--; si--; j++; }
    if (j < 16 && e < broken && (unsigned)v < (unsigned)NP)
        g_idx[(((size_t)b * NP + v) << 4) + j] = tg[e];
}

// ---------------------------------------------------------------------------
// FUSED transpose + per-point precompute (v2).
// Block 256 thr / 32 points. Dup'd weights staged to smem; compute packs 2
// points per thread (fma2), weight loads are 2-distinct-address LDS.128.
// Dynamic smem layout (bytes):
//   0      tile  float[32][33]   (4224)
//   4224   tileP u64  [32][16]   (4096)
//   8320   sWD   u64  [4096]     (32768)
//   41088  obuf  float[128][34]  (17408)   total 58496 B
// ---------------------------------------------------------------------------
#define TPRE_SMEM 58496

__global__ void __launch_bounds__(256) transpre_kernel(
    const float* __restrict__ f,
    const float* __restrict__ bb0, const float* __restrict__ sbc)
{
    extern __shared__ char smraw[];
    float (*tile)[33] = (float(*)[33])smraw;
    u64*  tileP       = (u64*)(smraw + 4224);           // [c][16]
    u64*  sWD         = (u64*)(smraw + 8320);           // [c][128]
    float (*obuf)[34] = (float(*)[34])(smraw + 41088);

    const int b  = blockIdx.y;
    const int p0 = blockIdx.x * 32;
    const int tid = threadIdx.x;
    const int tx = tid & 31, ty = tid >> 5;   // (32, 8)

    // stage dup'd weights (coalesced u64 loads)
    for (int i = tid; i < 4096; i += 256)
        sWD[i] = g_wD[i];

    // transpose into tile + write featT
    #pragma unroll
    for (int i = 0; i < 32; i += 8)
        tile[ty + i][tx] = f[((size_t)b * CH + ty + i) * NP + p0 + tx];
    __syncthreads();
    #pragma unroll
    for (int i = 0; i < 32; i += 8)
        g_featT[((size_t)b * NP + p0 + ty + i) * CH + tx] = tile[tx][ty + i];

    // build packed point-pairs tileP[c][pp] = (f[c][2pp], f[c][2pp+1])
    for (int i = tid; i < 512; i += 256) {
        int c = i >> 4, pp = i & 15;
        tileP[c * 16 + pp] = pack2(tile[c][2 * pp], tile[c][2 * pp + 1]);
    }
    __syncthreads();

    // compute: thread -> point-pair (tid&15), 8 outputs ((tid>>4)*8)
    {
        const int pp  = tid & 15;
        const int og0 = (tid >> 4) * 8;
        u64 acc[8];
        #pragma unroll
        for (int j = 0; j < 8; j++) acc[j] = 0ull;
        #pragma unroll 4
        for (int c = 0; c < 32; c++) {
            u64 xc = tileP[c * 16 + pp];
            const ulonglong2* wq = (const ulonglong2*)(sWD + c * 128 + og0);
            #pragma unroll
            for (int q = 0; q < 4; q++) {
                ulonglong2 wv = wq[q];
                acc[2*q]   = fma2(wv.x, xc, acc[2*q]);
                acc[2*q+1] = fma2(wv.y, xc, acc[2*q+1]);
            }
        }
        #pragma unroll
        for (int j = 0; j < 8; j++)
            *(u64*)&obuf[og0 + j][2 * pp] = acc[j];   // (pt 2pp, 2pp+1); stride 34 keeps 8B align
    }
    __syncthreads();

    // emit gY0 / gA / gSC (coalesced)
    const size_t rowbase = (size_t)b * NP + p0;
    for (int i = tid; i < 1024; i += 256) {
        int pt = i >> 5, c = i & 31;
        float y = obuf[c][pt];
        gY0[(rowbase + pt) * 32 + c] = y;
        gA [(rowbase + pt) * 32 + c] = obuf[32 + c][pt] + bb0[c] - y;
    }
    for (int i = tid; i < 2048; i += 256) {
        int pt = i >> 6, o = i & 63;
        gSC[(rowbase + pt) * 64 + o] = obuf[64 + o][pt] + sbc[o];
    }
}

// ---------------------------------------------------------------------------
// GEMM stage (scales pre-folded): o-sliced warps; weights [k][o] uniform
// LDG.128.  MODE 1: dst[o][r] = relu(acc + b[o]);
//           MODE 2: red[o][pt] = sum over rows of relu(acc + b[o])
// ---------------------------------------------------------------------------
template<int MODE>
__device__ __forceinline__ void gemm_stage(
    const float* __restrict__ src,   // [32][256] smem
    float*       __restrict__ dst,   // smem
    const float* __restrict__ WkT,   // global, [k][Ototal]
    int OSTR, int o0,
    const float* __restrict__ bias,
    int lane)
{
    u64 acc[8][4];
    #pragma unroll
    for (int o = 0; o < 8; o++)
        #pragma unroll
        for (int j = 0; j < 4; j++) acc[o][j] = 0ull;

    const float* xb = src + lane * 4;
    const float* wb = WkT + o0;

    #pragma unroll 4
    for (int k = 0; k < 32; k++) {
        u64 xp[4];
        {
            ulonglong2 x0 = *(const ulonglong2*)(xb + k * RR);
            ulonglong2 x1 = *(const ulonglong2*)(xb + k * RR + 128);
            xp[0] = x0.x; xp[1] = x0.y; xp[2] = x1.x; xp[3] = x1.y;
        }
        const float4* w4 = (const float4*)(wb + k * OSTR);
        float4 wa = __ldg(w4);
        float4 wc = __ldg(w4 + 1);
        u64 wd[8] = { pack2(wa.x,wa.x), pack2(wa.y,wa.y),
                      pack2(wa.z,wa.z), pack2(wa.w,wa.w),
                      pack2(wc.x,wc.x), pack2(wc.y,wc.y),
                      pack2(wc.z,wc.z), pack2(wc.w,wc.w) };
        #pragma unroll
        for (int o = 0; o < 8; o++) {
            acc[o][0] = fma2(wd[o], xp[0], acc[o][0]);
            acc[o][1] = fma2(wd[o], xp[1], acc[o][1]);
            acc[o][2] = fma2(wd[o], xp[2], acc[o][2]);
            acc[o][3] = fma2(wd[o], xp[3], acc[o][3]);
        }
    }

    const int ptq = lane >> 2;

    #pragma unroll
    for (int o = 0; o < 8; o++) {
        int og = o0 + o;
        float bv = bias[og];
        if (MODE == 2) {
            #pragma unroll
            for (int g = 0; g < 2; g++) {
                float h0, h1, h2, h3;
                unpack2(acc[o][2*g],   h0, h1);
                unpack2(acc[o][2*g+1], h2, h3);
                float pa = fmaxf(h0 + bv, 0.f) + fmaxf(h1 + bv, 0.f)
                         + fmaxf(h2 + bv, 0.f) + fmaxf(h3 + bv, 0.f);
                pa += __shfl_xor_sync(0xffffffffu, pa, 1);
                pa += __shfl_xor_sync(0xffffffffu, pa, 2);
                if ((lane & 3) == 0)
                    dst[og * TP + g * 8 + ptq] = pa;
            }
        } else {
            #pragma unroll
            for (int g = 0; g < 2; g++) {
                float h0, h1, h2, h3;
                unpack2(acc[o][2*g],   h0, h1);
                unpack2(acc[o][2*g+1], h2, h3);
                h0 = fmaxf(h0 + bv, 0.f);
                h1 = fmaxf(h1 + bv, 0.f);
                h2 = fmaxf(h2 + bv, 0.f);
                h3 = fmaxf(h3 + bv, 0.f);
                *(float4*)(dst + og * RR + g * 128 + lane * 4)
                    = make_float4(h0, h1, h2, h3);
            }
        }
    }
}

// ---------------------------------------------------------------------------
// Main kernel, 128 threads, TP=16 points (256 rows), 3 CTAs/SM.
// Smem (float offsets), 17504 floats = 68.4 KB:
//   0 sb1[32]  32 sb2[64]  96 red[64][16]  1120 XA[32][256]  9312 XB[32][256]
// ---------------------------------------------------------------------------
#define SMEM_FLOATS 17504

__global__ void __launch_bounds__(128, 3) main_kernel(
    const float* __restrict__ bb1, const float* __restrict__ bb2,
    float* __restrict__ out)
{
    extern __shared__ float sm[];
    float* sb1 = sm;
    float* sb2 = sm + 32;
    float* red = sm + 96;
    float* XA  = sm + 1120;
    float* XB  = sm + 9312;

    const int tid  = threadIdx.x;
    const int base = blockIdx.x * TP;
    const int b    = base >> 12;
    const int p0   = base & (NP - 1);

    if (tid < 32)      sb1[tid] = bb1[tid];
    else if (tid < 96) { int o = tid - 32; sb2[o] = bb2[o] * (1.0f / 16.0f); }

    // ---- staging: h0 = relu(Y0s[q] + A[p]) directly into XB [o][r] ----
    {
        int r0s = tid * 2;
        int pt  = r0s >> 4;
        int k0  = r0s & 15;
        size_t rowp = (size_t)b * NP + (p0 + pt);
        int2 qq = *(const int2*)(g_idx + (rowp << 4) + k0);
        const ulonglong2* Ap  = (const ulonglong2*)(gA  + rowp * 32);
        const ulonglong2* Yq0 = (const ulonglong2*)(gY0 + ((size_t)b * NP + qq.x) * 32);
        const ulonglong2* Yq1 = (const ulonglong2*)(gY0 + ((size_t)b * NP + qq.y) * 32);
        #pragma unroll
        for (int jj = 0; jj < 8; jj++) {
            ulonglong2 av = Ap[jj];
            ulonglong2 y0 = Yq0[jj];
            ulonglong2 y1 = Yq1[jj];
            int o = jj * 4;
            {
                u64 c0 = add2(y0.x, av.x), c1 = add2(y1.x, av.x);
                float a0, b0_, a1, b1_;
                unpack2(c0, a0, b0_); unpack2(c1, a1, b1_);
                *(u64*)(XB + (o+0) * RR + r0s) = pack2(fmaxf(a0, 0.f), fmaxf(a1, 0.f));
                *(u64*)(XB + (o+1) * RR + r0s) = pack2(fmaxf(b0_, 0.f), fmaxf(b1_, 0.f));
            }
            {
                u64 c0 = add2(y0.y, av.y), c1 = add2(y1.y, av.y);
                float a0, b0_, a1, b1_;
                unpack2(c0, a0, b0_); unpack2(c1, a1, b1_);
                *(u64*)(XB + (o+2) * RR + r0s) = pack2(fmaxf(a0, 0.f), fmaxf(a1, 0.f));
                *(u64*)(XB + (o+3) * RR + r0s) = pack2(fmaxf(b0_, 0.f), fmaxf(b1_, 0.f));
            }
        }
    }
    __syncthreads();

    const int w_   = tid >> 5;
    const int lane = tid & 31;

    gemm_stage<1>(XB, XA, g_w1T, 32, w_ * 8, sb1, lane);
    __syncthreads();
    gemm_stage<2>(XA, red, g_w2T, 64, w_ * 8,      sb2, lane);
    gemm_stage<2>(XA, red, g_w2T, 64, 32 + w_ * 8, sb2, lane);
    __syncthreads();

    // ---- epilogue: out = relu(SC[p] + red) ----
    {
        int pt  = tid & 15;
        int o0s = (tid >> 4) * 8;
        const float4* scp = (const float4*)(gSC + ((size_t)b * NP + p0 + pt) * 64 + o0s);
        float4 s0 = scp[0], s1 = scp[1];
        float scv[8] = { s0.x, s0.y, s0.z, s0.w, s1.x, s1.y, s1.z, s1.w };
        #pragma unroll
        for (int j = 0; j < 8; j++) {
            int o = o0s + j;
            float v = scv[j] + red[o * TP + pt];
            out[((size_t)b * 64 + o) * NP + p0 + pt] = fmaxf(v, 0.f);
        }
    }
}

// ---------------------------------------------------------------------------
extern "C" void kernel_launch(void* const* d_in, const int* in_sizes, int n_in,
                              void* d_out, int out_size)
{
    (void)in_sizes; (void)n_in; (void)out_size;
    const float* features = (const float*)d_in[1];
    const int*   ef       = (const int*)d_in[2];

    static bool init_done = false;
    static cudaStream_t s_edge;
    static cudaEvent_t ev_fork, ev_join;
    if (!init_done) {
        cudaFuncSetAttribute(main_kernel,
                             cudaFuncAttributeMaxDynamicSharedMemorySize,
                             SMEM_FLOATS * (int)sizeof(float));
        cudaFuncSetAttribute(transpre_kernel,
                             cudaFuncAttributeMaxDynamicSharedMemorySize,
                             TPRE_SMEM);
        cudaStreamCreateWithFlags(&s_edge, cudaStreamNonBlocking);
        cudaEventCreateWithFlags(&ev_fork, cudaEventDisableTiming);
        cudaEventCreateWithFlags(&ev_join, cudaEventDisableTiming);
        init_done = true;
    }

    // fork: edge pipeline on side stream, overlapped with weight/feature prep
    cudaEventRecord(ev_fork, 0);
    cudaStreamWaitEvent(s_edge, ev_fork, 0);
    prep_kernel<<<BATCH * 256, 256, 0, s_edge>>>(ef);
    {
        dim3 tg(EDG / 256, BATCH);
        scatter_kernel<<<tg, 256, 0, s_edge>>>(ef);
    }
    cudaEventRecord(ev_join, s_edge);

    wprep_kernel<<<28, 256>>>((const float*)d_in[3], (const float*)d_in[6],
                              (const float*)d_in[9], (const float*)d_in[12],
                              (const float*)d_in[4], (const float*)d_in[13],
                              (const float*)d_in[7], (const float*)d_in[10]);
    {
        dim3 tg(NP / 32, BATCH);
        transpre_kernel<<<tg, 256, TPRE_SMEM>>>(features, (const float*)d_in[5],
                                                (const float*)d_in[14]);
    }

    // join, then main
    cudaStreamWaitEvent(0, ev_join, 0);
    main_kernel<<<(BATCH * NP) / TP, 128, SMEM_FLOATS * sizeof(float)>>>(
        (const float*)d_in[8], (const float*)d_in[11],
        (float*)d_out);
}

// round 16
// speedup vs baseline: 1.0764x; 1.0764x over previous
#include <cuda_runtime.h>

#define K1v 16
#define BATCH 16
#define CH 32
#define NP 4096
#define EDG (NP*K1v)          // 65536
#define TP 16                 // points per CTA (main)
#define RR 256
#define PPB 256               // points per CTA (pre)
#define OBS 260               // obuf row stride (mult of 4)
#define INVC 0.9999950000374997f  // 1/sqrt(1+1e-5)

typedef unsigned long long u64;

// Scratch (no cudaMalloc allowed)
__device__ int   g_idx[BATCH*NP*K1v];            // 4 MB
__device__ int   g_brk[BATCH*256];
__device__ __align__(16) float g_wPre[4096];     // [c][128o]: ss0*W0h | ss0*W0l | ssc*SW
__device__ __align__(16) float g_w1T[1024];      // (g1*INVC)*W1   [k][32o]
__device__ __align__(16) float g_w2T[2048];      // (g2*INVC/16)*W2 [k][64o]
__device__ __align__(16) float gY0[BATCH*NP*32]; // ss0*(W0h f)   8 MB
__device__ __align__(16) float gA [BATCH*NP*32]; // pb0 - Y0s     8 MB
__device__ __align__(16) float gSC[BATCH*NP*64]; // shortcut     16 MB

__device__ __forceinline__ u64 fma2(u64 a, u64 b, u64 c) {
    u64 d;
    asm("fma.rn.f32x2 %0, %1, %2, %3;" : "=l"(d) : "l"(a), "l"(b), "l"(c));
    return d;
}
__device__ __forceinline__ u64 add2(u64 a, u64 b) {
    u64 d;
    asm("add.rn.f32x2 %0, %1, %2;" : "=l"(d) : "l"(a), "l"(b));
    return d;
}
__device__ __forceinline__ u64 pack2(float x, float y) {
    u64 d;
    asm("mov.b64 %0, {%1, %2};" : "=l"(d) : "f"(x), "f"(y));
    return d;
}
__device__ __forceinline__ void unpack2(u64 v, float& x, float& y) {
    asm("mov.b64 {%0, %1}, %2;" : "=f"(x), "=f"(y) : "l"(v));
}

// ---------------------------------------------------------------------------
// Weight prep: g_wPre [c][128] (scales folded); w1T/w2T [k][o] scale-folded.
// ---------------------------------------------------------------------------
__global__ void wprep_kernel(const float* __restrict__ W0, const float* __restrict__ W1,
                             const float* __restrict__ W2, const float* __restrict__ SW,
                             const float* __restrict__ g0, const float* __restrict__ sg,
                             const float* __restrict__ g1, const float* __restrict__ g2) {
    int t = blockIdx.x * 256 + threadIdx.x;   // 0..7167
    if (t < 4096) {
        int c = t >> 7, j = t & 127;
        float v;
        if (j < 32)       v = g0[j] * INVC * W0[j * 64 + 32 + c];
        else if (j < 64)  { int o = j - 32; v = g0[o] * INVC * W0[o * 64 + c]; }
        else              { int o = j - 64; v = sg[o] * INVC * SW[o * 32 + c]; }
        g_wPre[t] = v;
    } else if (t < 5120) {
        int i = t - 4096, k = i >> 5, o = i & 31;
        g_w1T[k * 32 + o] = g1[o] * INVC * W1[o * 32 + k];
    } else if (t < 7168) {
        int i = t - 5120, k = i >> 6, o = i & 63;
        g_w2T[k * 64 + o] = g2[o] * (INVC / 16.0f) * W2[o * 32 + k];
    }
}

// ---------------------------------------------------------------------------
// Edge preprocessing: prep (defaults + per-chunk break) -> scatter
// ---------------------------------------------------------------------------
__global__ void prep_kernel(const int* __restrict__ ef) {
    const int blk   = blockIdx.x;
    const int b     = blk >> 8;
    const int chunk = blk & 255;
    const int t     = threadIdx.x;
    const int e     = chunk * 256 + t;

    g_idx[(b << 16) | e] = NP - K1v + (e & 15);

    const int* __restrict__ pf = ef + (size_t)b * 2 * EDG;
    int brk = EDG;
    if (e > 0 && pf[e] == 0 && pf[e - 1] != 0) brk = e;

    __shared__ int s[256];
    s[t] = brk;
    __syncthreads();
    #pragma unroll
    for (int off = 128; off > 0; off >>= 1) {
        if (t < off) s[t] = min(s[t], s[t + off]);
        __syncthreads();
    }
    if (t == 0) g_brk[b * 256 + chunk] = s[0];
}

__global__ void scatter_kernel(const int* __restrict__ ef) {
    const int b  = blockIdx.y;
    const int e0 = blockIdx.x * 256;
    const int t  = threadIdx.x;
    const int e  = e0 + t;
    const int* __restrict__ pf = ef + (size_t)b * 2 * EDG;
    const int* __restrict__ tg = pf + EDG;

    __shared__ int s[272];
    __shared__ int sm2[256];
    sm2[t] = g_brk[b * 256 + t];
    for (int i = t; i < 272; i += 256) {
        int src = e0 - 16 + i;
        s[i] = (src >= 0) ? pf[src] : -1;
    }
    __syncthreads();
    #pragma unroll
    for (int off = 128; off > 0; off >>= 1) {
        if (t < off) sm2[t] = min(sm2[t], sm2[t + off]);
        __syncthreads();
    }
    const int broken = sm2[0];

    int v = s[t + 16];
    int j = 0, m = e, si = t + 16;
    while (m > 0 && j < 16 && s[si - 1] == v) { m--; si--; j++; }
    if (j < 16 && e < broken && (unsigned)v < (unsigned)NP)
        g_idx[(((size_t)b * NP + v) << 4) + j] = tg[e];
}

// ---------------------------------------------------------------------------
// Pre-GEMM pass: 8 outputs per warp over 256 points (raw accumulation, no
// bias/relu). Weights [c][128o] uniform LDG.128. X [32][256] smem.
// ---------------------------------------------------------------------------
__device__ __forceinline__ void pre_pass(
    const float* __restrict__ X,     // [32][256] smem
    float*       __restrict__ dst,   // obuf, row stride OBS, 32 rows
    int wbase,                       // 0 / 32 / 64 / 96 (global o base of pass)
    int ol0,                         // warp-local o base (w_*8)
    int lane)
{
    u64 acc[8][4];
    #pragma unroll
    for (int o = 0; o < 8; o++)
        #pragma unroll
        for (int j = 0; j < 4; j++) acc[o][j] = 0ull;

    const float* xb = X + lane * 4;
    const float* wb = g_wPre + wbase + ol0;

    #pragma unroll 4
    for (int k = 0; k < 32; k++) {
        u64 xp[4];
        {
            ulonglong2 x0 = *(const ulonglong2*)(xb + k * 256);
            ulonglong2 x1 = *(const ulonglong2*)(xb + k * 256 + 128);
            xp[0] = x0.x; xp[1] = x0.y; xp[2] = x1.x; xp[3] = x1.y;
        }
        const float4* w4 = (const float4*)(wb + k * 128);
        float4 wa = __ldg(w4);
        float4 wc = __ldg(w4 + 1);
        u64 wd[8] = { pack2(wa.x,wa.x), pack2(wa.y,wa.y),
                      pack2(wa.z,wa.z), pack2(wa.w,wa.w),
                      pack2(wc.x,wc.x), pack2(wc.y,wc.y),
                      pack2(wc.z,wc.z), pack2(wc.w,wc.w) };
        #pragma unroll
        for (int o = 0; o < 8; o++) {
            acc[o][0] = fma2(wd[o], xp[0], acc[o][0]);
            acc[o][1] = fma2(wd[o], xp[1], acc[o][1]);
            acc[o][2] = fma2(wd[o], xp[2], acc[o][2]);
            acc[o][3] = fma2(wd[o], xp[3], acc[o][3]);
        }
    }

    #pragma unroll
    for (int o = 0; o < 8; o++) {
        #pragma unroll
        for (int g = 0; g < 2; g++) {
            float h0, h1, h2, h3;
            unpack2(acc[o][2*g],   h0, h1);
            unpack2(acc[o][2*g+1], h2, h3);
            *(float4*)(dst + (ol0 + o) * OBS + g * 128 + lane * 4)
                = make_float4(h0, h1, h2, h3);
        }
    }
}

// ---------------------------------------------------------------------------
// pre_kernel: per-point precompute as GEMM, directly from features (B,C,P).
// 256 points per CTA, 128 threads, 4 passes of 32 outputs.
// Smem: X float[32][256] (32KB) + obufA/obufB float[32][260] (33.3KB ea) = 98.6KB
// ---------------------------------------------------------------------------
#define PRE_SMEM ((32*256 + 2*32*OBS) * 4)

__global__ void __launch_bounds__(128, 2) pre_kernel(
    const float* __restrict__ f,
    const float* __restrict__ bb0, const float* __restrict__ sbc)
{
    extern __shared__ float sm[];
    float* X     = sm;                 // [32][256]
    float* obufA = sm + 32 * 256;      // [32][OBS]
    float* obufB = obufA + 32 * OBS;   // [32][OBS]

    const int tid = threadIdx.x;
    const int b   = blockIdx.y;
    const int p0  = blockIdx.x * PPB;

    // stage X[c][pt] straight from features (already c-major)
    {
        const float4* src = (const float4*)(f + ((size_t)b * CH) * NP + p0);
        float4* dstx = (float4*)X;
        // row c: src offset c*(NP/4), dst offset c*64
        for (int i = tid; i < 2048; i += 128) {
            int c = i >> 6, j = i & 63;
            dstx[c * 64 + j] = src[(size_t)c * (NP / 4) + j];
        }
    }
    __syncthreads();

    const int w_   = tid >> 5;
    const int lane = tid & 31;
    const int ol0  = w_ * 8;

    // passes 0,1: Y0 (o 0-31) -> obufA ; pb0raw (o 32-63) -> obufB
    pre_pass(X, obufA, 0,  ol0, lane);
    pre_pass(X, obufB, 32, ol0, lane);
    __syncthreads();

    const size_t rowbase = (size_t)b * NP + p0;

    // emit gY0 / gA
    for (int i = tid; i < 32 * PPB; i += 128) {
        int pt = i >> 5, c = i & 31;
        float y = obufA[c * OBS + pt];
        gY0[(rowbase + pt) * 32 + c] = y;
        gA [(rowbase + pt) * 32 + c] = obufB[c * OBS + pt] + bb0[c] - y;
    }
    __syncthreads();

    // passes 2,3: SC low (o 64-95) -> obufA ; SC high (o 96-127) -> obufB
    pre_pass(X, obufA, 64, ol0, lane);
    pre_pass(X, obufB, 96, ol0, lane);
    __syncthreads();

    // emit gSC
    for (int i = tid; i < 64 * PPB; i += 128) {
        int pt = i >> 6, o = i & 63;
        float v = (o < 32) ? obufA[o * OBS + pt] : obufB[(o - 32) * OBS + pt];
        gSC[(rowbase + pt) * 64 + o] = v + sbc[o];
    }
}

// ---------------------------------------------------------------------------
// GEMM stage (scales pre-folded): o-sliced warps; weights [k][o] uniform
// LDG.128.  MODE 1: dst[o][r] = relu(acc + b[o]);
//           MODE 2: red[o][pt] = sum over rows of relu(acc + b[o])
// ---------------------------------------------------------------------------
template<int MODE>
__device__ __forceinline__ void gemm_stage(
    const float* __restrict__ src,   // [32][256] smem
    float*       __restrict__ dst,   // smem
    const float* __restrict__ WkT,   // global, [k][Ototal]
    int OSTR, int o0,
    const float* __restrict__ bias,
    int lane)
{
    u64 acc[8][4];
    #pragma unroll
    for (int o = 0; o < 8; o++)
        #pragma unroll
        for (int j = 0; j < 4; j++) acc[o][j] = 0ull;

    const float* xb = src + lane * 4;
    const float* wb = WkT + o0;

    #pragma unroll 4
    for (int k = 0; k < 32; k++) {
        u64 xp[4];
        {
            ulonglong2 x0 = *(const ulonglong2*)(xb + k * RR);
            ulonglong2 x1 = *(const ulonglong2*)(xb + k * RR + 128);
            xp[0] = x0.x; xp[1] = x0.y; xp[2] = x1.x; xp[3] = x1.y;
        }
        const float4* w4 = (const float4*)(wb + k * OSTR);
        float4 wa = __ldg(w4);
        float4 wc = __ldg(w4 + 1);
        u64 wd[8] = { pack2(wa.x,wa.x), pack2(wa.y,wa.y),
                      pack2(wa.z,wa.z), pack2(wa.w,wa.w),
                      pack2(wc.x,wc.x), pack2(wc.y,wc.y),
                      pack2(wc.z,wc.z), pack2(wc.w,wc.w) };
        #pragma unroll
        for (int o = 0; o < 8; o++) {
            acc[o][0] = fma2(wd[o], xp[0], acc[o][0]);
            acc[o][1] = fma2(wd[o], xp[1], acc[o][1]);
            acc[o][2] = fma2(wd[o], xp[2], acc[o][2]);
            acc[o][3] = fma2(wd[o], xp[3], acc[o][3]);
        }
    }

    const int ptq = lane >> 2;

    #pragma unroll
    for (int o = 0; o < 8; o++) {
        int og = o0 + o;
        float bv = bias[og];
        if (MODE == 2) {
            #pragma unroll
            for (int g = 0; g < 2; g++) {
                float h0, h1, h2, h3;
                unpack2(acc[o][2*g],   h0, h1);
                unpack2(acc[o][2*g+1], h2, h3);
                float pa = fmaxf(h0 + bv, 0.f) + fmaxf(h1 + bv, 0.f)
                         + fmaxf(h2 + bv, 0.f) + fmaxf(h3 + bv, 0.f);
                pa += __shfl_xor_sync(0xffffffffu, pa, 1);
                pa += __shfl_xor_sync(0xffffffffu, pa, 2);
                if ((lane & 3) == 0)
                    dst[og * TP + g * 8 + ptq] = pa;
            }
        } else {
            #pragma unroll
            for (int g = 0; g < 2; g++) {
                float h0, h1, h2, h3;
                unpack2(acc[o][2*g],   h0, h1);
                unpack2(acc[o][2*g+1], h2, h3);
                h0 = fmaxf(h0 + bv, 0.f);
                h1 = fmaxf(h1 + bv, 0.f);
                h2 = fmaxf(h2 + bv, 0.f);
                h3 = fmaxf(h3 + bv, 0.f);
                *(float4*)(dst + og * RR + g * 128 + lane * 4)
                    = make_float4(h0, h1, h2, h3);
            }
        }
    }
}

// ---------------------------------------------------------------------------
// Main kernel, 128 threads, TP=16 points (256 rows), 3 CTAs/SM.
// ---------------------------------------------------------------------------
#define SMEM_FLOATS 17504

__global__ void __launch_bounds__(128, 3) main_kernel(
    const float* __restrict__ bb1, const float* __restrict__ bb2,
    float* __restrict__ out)
{
    extern __shared__ float sm[];
    float* sb1 = sm;
    float* sb2 = sm + 32;
    float* red = sm + 96;
    float* XA  = sm + 1120;
    float* XB  = sm + 9312;

    const int tid  = threadIdx.x;
    const int base = blockIdx.x * TP;
    const int b    = base >> 12;
    const int p0   = base & (NP - 1);

    if (tid < 32)      sb1[tid] = bb1[tid];
    else if (tid < 96) { int o = tid - 32; sb2[o] = bb2[o] * (1.0f / 16.0f); }

    // ---- staging: h0 = relu(Y0s[q] + A[p]) directly into XB [o][r] ----
    {
        int r0s = tid * 2;
        int pt  = r0s >> 4;
        int k0  = r0s & 15;
        size_t rowp = (size_t)b * NP + (p0 + pt);
        int2 qq = *(const int2*)(g_idx + (rowp << 4) + k0);
        const ulonglong2* Ap  = (const ulonglong2*)(gA  + rowp * 32);
        const ulonglong2* Yq0 = (const ulonglong2*)(gY0 + ((size_t)b * NP + qq.x) * 32);
        const ulonglong2* Yq1 = (const ulonglong2*)(gY0 + ((size_t)b * NP + qq.y) * 32);
        #pragma unroll
        for (int jj = 0; jj < 8; jj++) {
            ulonglong2 av = Ap[jj];
            ulonglong2 y0 = Yq0[jj];
            ulonglong2 y1 = Yq1[jj];
            int o = jj * 4;
            {
                u64 c0 = add2(y0.x, av.x), c1 = add2(y1.x, av.x);
                float a0, b0_, a1, b1_;
                unpack2(c0, a0, b0_); unpack2(c1, a1, b1_);
                *(u64*)(XB + (o+0) * RR + r0s) = pack2(fmaxf(a0, 0.f), fmaxf(a1, 0.f));
                *(u64*)(XB + (o+1) * RR + r0s) = pack2(fmaxf(b0_, 0.f), fmaxf(b1_, 0.f));
            }
            {
                u64 c0 = add2(y0.y, av.y), c1 = add2(y1.y, av.y);
                float a0, b0_, a1, b1_;
                unpack2(c0, a0, b0_); unpack2(c1, a1, b1_);
                *(u64*)(XB + (o+2) * RR + r0s) = pack2(fmaxf(a0, 0.f), fmaxf(a1, 0.f));
                *(u64*)(XB + (o+3) * RR + r0s) = pack2(fmaxf(b0_, 0.f), fmaxf(b1_, 0.f));
            }
        }
    }
    __syncthreads();

    const int w_   = tid >> 5;
    const int lane = tid & 31;

    gemm_stage<1>(XB, XA, g_w1T, 32, w_ * 8, sb1, lane);
    __syncthreads();
    gemm_stage<2>(XA, red, g_w2T, 64, w_ * 8,      sb2, lane);
    gemm_stage<2>(XA, red, g_w2T, 64, 32 + w_ * 8, sb2, lane);
    __syncthreads();

    // ---- epilogue: out = relu(SC[p] + red) ----
    {
        int pt  = tid & 15;
        int o0s = (tid >> 4) * 8;
        const float4* scp = (const float4*)(gSC + ((size_t)b * NP + p0 + pt) * 64 + o0s);
        float4 s0 = scp[0], s1 = scp[1];
        float scv[8] = { s0.x, s0.y, s0.z, s0.w, s1.x, s1.y, s1.z, s1.w };
        #pragma unroll
        for (int j = 0; j < 8; j++) {
            int o = o0s + j;
            float v = scv[j] + red[o * TP + pt];
            out[((size_t)b * 64 + o) * NP + p0 + pt] = fmaxf(v, 0.f);
        }
    }
}

// ---------------------------------------------------------------------------
extern "C" void kernel_launch(void* const* d_in, const int* in_sizes, int n_in,
                              void* d_out, int out_size)
{
    (void)in_sizes; (void)n_in; (void)out_size;
    const float* features = (const float*)d_in[1];
    const int*   ef       = (const int*)d_in[2];

    static bool init_done = false;
    static cudaStream_t s_edge;
    static cudaEvent_t ev_fork, ev_join;
    if (!init_done) {
        cudaFuncSetAttribute(main_kernel,
                             cudaFuncAttributeMaxDynamicSharedMemorySize,
                             SMEM_FLOATS * (int)sizeof(float));
        cudaFuncSetAttribute(pre_kernel,
                             cudaFuncAttributeMaxDynamicSharedMemorySize,
                             PRE_SMEM);
        cudaStreamCreateWithFlags(&s_edge, cudaStreamNonBlocking);
        cudaEventCreateWithFlags(&ev_fork, cudaEventDisableTiming);
        cudaEventCreateWithFlags(&ev_join, cudaEventDisableTiming);
        init_done = true;
    }

    // fork: edge pipeline on side stream, overlapped with weight/point prep
    cudaEventRecord(ev_fork, 0);
    cudaStreamWaitEvent(s_edge, ev_fork, 0);
    prep_kernel<<<BATCH * 256, 256, 0, s_edge>>>(ef);
    {
        dim3 tg(EDG / 256, BATCH);
        scatter_kernel<<<tg, 256, 0, s_edge>>>(ef);
    }
    cudaEventRecord(ev_join, s_edge);

    wprep_kernel<<<28, 256>>>((const float*)d_in[3], (const float*)d_in[6],
                              (const float*)d_in[9], (const float*)d_in[12],
                              (const float*)d_in[4], (const float*)d_in[13],
                              (const float*)d_in[7], (const float*)d_in[10]);
    {
        dim3 tg(NP / PPB, BATCH);   // (16, 16)
        pre_kernel<<<tg, 128, PRE_SMEM>>>(features, (const float*)d_in[5],
                                          (const float*)d_in[14]);
    }

    // join, then main
    cudaStreamWaitEvent(0, ev_join, 0);
    main_kernel<<<(BATCH * NP) / TP, 128, SMEM_FLOATS * sizeof(float)>>>(
        (const float*)d_in[8], (const float*)d_in[11],
        (float*)d_out);
}

// round 17
// speedup vs baseline: 1.0823x; 1.0055x over previous
#include <cuda_runtime.h>

#define K1v 16
#define BATCH 16
#define CH 32
#define NP 4096
#define EDG (NP*K1v)          // 65536
#define TP 16                 // points per CTA (main)
#define RR 256
#define PPB 256               // points per CTA (pre)
#define OBS 260               // obuf row stride
#define INVC 0.9999950000374997f  // 1/sqrt(1+1e-5)

typedef unsigned long long u64;

// Scratch (no cudaMalloc allowed)
__device__ int   g_idx[BATCH*NP*K1v];            // 4 MB
__device__ int   g_brk[BATCH*256];
__device__ __align__(16) float g_wPre[4096];     // [c][128o]: ss0*W0h | ss0*W0l | ssc*SW
__device__ __align__(16) float g_w1T[1024];      // (g1*INVC)*W1   [k][32o]
__device__ __align__(16) float g_w2T[2048];      // (g2*INVC/16)*W2 [k][64o]
__device__ __align__(16) float gY0[BATCH*NP*32]; // 8 MB
__device__ __align__(16) float gA [BATCH*NP*32]; // 8 MB
__device__ __align__(16) float gSC[BATCH*NP*64]; // 16 MB

__device__ __forceinline__ u64 fma2(u64 a, u64 b, u64 c) {
    u64 d;
    asm("fma.rn.f32x2 %0, %1, %2, %3;" : "=l"(d) : "l"(a), "l"(b), "l"(c));
    return d;
}
__device__ __forceinline__ u64 add2(u64 a, u64 b) {
    u64 d;
    asm("add.rn.f32x2 %0, %1, %2;" : "=l"(d) : "l"(a), "l"(b));
    return d;
}
__device__ __forceinline__ u64 pack2(float x, float y) {
    u64 d;
    asm("mov.b64 %0, {%1, %2};" : "=l"(d) : "f"(x), "f"(y));
    return d;
}
__device__ __forceinline__ void unpack2(u64 v, float& x, float& y) {
    asm("mov.b64 {%0, %1}, %2;" : "=f"(x), "=f"(y) : "l"(v));
}

// ---------------------------------------------------------------------------
__global__ void wprep_kernel(const float* __restrict__ W0, const float* __restrict__ W1,
                             const float* __restrict__ W2, const float* __restrict__ SW,
                             const float* __restrict__ g0, const float* __restrict__ sg,
                             const float* __restrict__ g1, const float* __restrict__ g2) {
    int t = blockIdx.x * 256 + threadIdx.x;   // 0..7167
    if (t < 4096) {
        int c = t >> 7, j = t & 127;
        float v;
        if (j < 32)       v = g0[j] * INVC * W0[j * 64 + 32 + c];
        else if (j < 64)  { int o = j - 32; v = g0[o] * INVC * W0[o * 64 + c]; }
        else              { int o = j - 64; v = sg[o] * INVC * SW[o * 32 + c]; }
        g_wPre[t] = v;
    } else if (t < 5120) {
        int i = t - 4096, k = i >> 5, o = i & 31;
        g_w1T[k * 32 + o] = g1[o] * INVC * W1[o * 32 + k];
    } else if (t < 7168) {
        int i = t - 5120, k = i >> 6, o = i & 63;
        g_w2T[k * 64 + o] = g2[o] * (INVC / 16.0f) * W2[o * 32 + k];
    }
}

// ---------------------------------------------------------------------------
// Edge preprocessing: prep (defaults + per-chunk break) -> scatter
// ---------------------------------------------------------------------------
__global__ void prep_kernel(const int* __restrict__ ef) {
    const int blk   = blockIdx.x;
    const int b     = blk >> 8;
    const int chunk = blk & 255;
    const int t     = threadIdx.x;
    const int e     = chunk * 256 + t;

    g_idx[(b << 16) | e] = NP - K1v + (e & 15);

    const int* __restrict__ pf = ef + (size_t)b * 2 * EDG;
    int brk = EDG;
    if (e > 0 && pf[e] == 0 && pf[e - 1] != 0) brk = e;

    __shared__ int s[256];
    s[t] = brk;
    __syncthreads();
    #pragma unroll
    for (int off = 128; off > 0; off >>= 1) {
        if (t < off) s[t] = min(s[t], s[t + off]);
        __syncthreads();
    }
    if (t == 0) g_brk[b * 256 + chunk] = s[0];
}

__global__ void scatter_kernel(const int* __restrict__ ef) {
    const int b  = blockIdx.y;
    const int e0 = blockIdx.x * 256;
    const int t  = threadIdx.x;
    const int e  = e0 + t;
    const int* __restrict__ pf = ef + (size_t)b * 2 * EDG;
    const int* __restrict__ tg = pf + EDG;

    __shared__ int s[272];
    __shared__ int sm2[256];
    sm2[t] = g_brk[b * 256 + t];
    for (int i = t; i < 272; i += 256) {
        int src = e0 - 16 + i;
        s[i] = (src >= 0) ? pf[src] : -1;
    }
    __syncthreads();
    #pragma unroll
    for (int off = 128; off > 0; off >>= 1) {
        if (t < off) sm2[t] = min(sm2[t], sm2[t + off]);
        __syncthreads();
    }
    const int broken = sm2[0];

    int v = s[t + 16];
    int j = 0, m = e, si = t + 16;
    while (m > 0 && j < 16 && s[si - 1] == v) { m--; si--; j++; }
    if (j < 16 && e < broken && (unsigned)v < (unsigned)NP)
        g_idx[(((size_t)b * NP + v) << 4) + j] = tg[e];
}

// ---------------------------------------------------------------------------
// Pre-GEMM pass (raw accumulation). Weights [c][128o] uniform LDG.128.
// ---------------------------------------------------------------------------
__device__ __forceinline__ void pre_pass(
    const float* __restrict__ X,     // [32][256] smem
    float*       __restrict__ dst,   // obuf, row stride OBS, 32 rows
    int wbase, int ol0, int lane)
{
    u64 acc[8][4];
    #pragma unroll
    for (int o = 0; o < 8; o++)
        #pragma unroll
        for (int j = 0; j < 4; j++) acc[o][j] = 0ull;

    const float* xb = X + lane * 4;
    const float* wb = g_wPre + wbase + ol0;

    #pragma unroll 4
    for (int k = 0; k < 32; k++) {
        u64 xp[4];
        {
            ulonglong2 x0 = *(const ulonglong2*)(xb + k * 256);
            ulonglong2 x1 = *(const ulonglong2*)(xb + k * 256 + 128);
            xp[0] = x0.x; xp[1] = x0.y; xp[2] = x1.x; xp[3] = x1.y;
        }
        const float4* w4 = (const float4*)(wb + k * 128);
        float4 wa = __ldg(w4);
        float4 wc = __ldg(w4 + 1);
        u64 wd[8] = { pack2(wa.x,wa.x), pack2(wa.y,wa.y),
                      pack2(wa.z,wa.z), pack2(wa.w,wa.w),
                      pack2(wc.x,wc.x), pack2(wc.y,wc.y),
                      pack2(wc.z,wc.z), pack2(wc.w,wc.w) };
        #pragma unroll
        for (int o = 0; o < 8; o++) {
            acc[o][0] = fma2(wd[o], xp[0], acc[o][0]);
            acc[o][1] = fma2(wd[o], xp[1], acc[o][1]);
            acc[o][2] = fma2(wd[o], xp[2], acc[o][2]);
            acc[o][3] = fma2(wd[o], xp[3], acc[o][3]);
        }
    }

    #pragma unroll
    for (int o = 0; o < 8; o++) {
        #pragma unroll
        for (int g = 0; g < 2; g++) {
            float h0, h1, h2, h3;
            unpack2(acc[o][2*g],   h0, h1);
            unpack2(acc[o][2*g+1], h2, h3);
            *(float4*)(dst + (ol0 + o) * OBS + g * 128 + lane * 4)
                = make_float4(h0, h1, h2, h3);
        }
    }
}

// ---------------------------------------------------------------------------
// pre_kernel (v2): 256 threads / 8 warps; warps 0-3 and 4-7 run the two
// passes of each round concurrently. bofs selects batch half.
// ---------------------------------------------------------------------------
#define PRE_SMEM ((32*256 + 2*32*OBS) * 4)

__global__ void __launch_bounds__(256) pre_kernel(
    const float* __restrict__ f,
    const float* __restrict__ bb0, const float* __restrict__ sbc,
    int bofs)
{
    extern __shared__ float sm[];
    float* X     = sm;                 // [32][256]
    float* obufA = sm + 32 * 256;      // [32][OBS]
    float* obufB = obufA + 32 * OBS;   // [32][OBS]

    const int tid = threadIdx.x;
    const int b   = blockIdx.y + bofs;
    const int p0  = blockIdx.x * PPB;

    // stage X[c][pt] straight from features (already c-major)
    {
        const float4* src = (const float4*)(f + ((size_t)b * CH) * NP + p0);
        float4* dstx = (float4*)X;
        for (int i = tid; i < 2048; i += 256) {
            int c = i >> 6, j = i & 63;
            dstx[c * 64 + j] = src[(size_t)c * (NP / 4) + j];
        }
    }
    __syncthreads();

    const int w_   = tid >> 5;
    const int lane = tid & 31;
    const int grp  = w_ >> 2;          // 0 -> obufA, 1 -> obufB
    const int ol0  = (w_ & 3) * 8;
    float* myObuf  = grp ? obufB : obufA;

    // round 1: Y0 (0-31) -> obufA ; pb0raw (32-63) -> obufB (concurrent)
    pre_pass(X, myObuf, grp * 32, ol0, lane);
    __syncthreads();

    const size_t rowbase = (size_t)b * NP + p0;
    for (int i = tid; i < 32 * PPB; i += 256) {
        int pt = i >> 5, c = i & 31;
        float y = obufA[c * OBS + pt];
        gY0[(rowbase + pt) * 32 + c] = y;
        gA [(rowbase + pt) * 32 + c] = obufB[c * OBS + pt] + bb0[c] - y;
    }
    __syncthreads();

    // round 2: SC low (64-95) -> obufA ; SC high (96-127) -> obufB
    pre_pass(X, myObuf, 64 + grp * 32, ol0, lane);
    __syncthreads();

    for (int i = tid; i < 64 * PPB; i += 256) {
        int pt = i >> 6, o = i & 63;
        float v = (o < 32) ? obufA[o * OBS + pt] : obufB[(o - 32) * OBS + pt];
        gSC[(rowbase + pt) * 64 + o] = v + sbc[o];
    }
}

// ---------------------------------------------------------------------------
// GEMM stage (scales pre-folded)
// ---------------------------------------------------------------------------
template<int MODE>
__device__ __forceinline__ void gemm_stage(
    const float* __restrict__ src,
    float*       __restrict__ dst,
    const float* __restrict__ WkT,
    int OSTR, int o0,
    const float* __restrict__ bias,
    int lane)
{
    u64 acc[8][4];
    #pragma unroll
    for (int o = 0; o < 8; o++)
        #pragma unroll
        for (int j = 0; j < 4; j++) acc[o][j] = 0ull;

    const float* xb = src + lane * 4;
    const float* wb = WkT + o0;

    #pragma unroll 4
    for (int k = 0; k < 32; k++) {
        u64 xp[4];
        {
            ulonglong2 x0 = *(const ulonglong2*)(xb + k * RR);
            ulonglong2 x1 = *(const ulonglong2*)(xb + k * RR + 128);
            xp[0] = x0.x; xp[1] = x0.y; xp[2] = x1.x; xp[3] = x1.y;
        }
        const float4* w4 = (const float4*)(wb + k * OSTR);
        float4 wa = __ldg(w4);
        float4 wc = __ldg(w4 + 1);
        u64 wd[8] = { pack2(wa.x,wa.x), pack2(wa.y,wa.y),
                      pack2(wa.z,wa.z), pack2(wa.w,wa.w),
                      pack2(wc.x,wc.x), pack2(wc.y,wc.y),
                      pack2(wc.z,wc.z), pack2(wc.w,wc.w) };
        #pragma unroll
        for (int o = 0; o < 8; o++) {
            acc[o][0] = fma2(wd[o], xp[0], acc[o][0]);
            acc[o][1] = fma2(wd[o], xp[1], acc[o][1]);
            acc[o][2] = fma2(wd[o], xp[2], acc[o][2]);
            acc[o][3] = fma2(wd[o], xp[3], acc[o][3]);
        }
    }

    const int ptq = lane >> 2;

    #pragma unroll
    for (int o = 0; o < 8; o++) {
        int og = o0 + o;
        float bv = bias[og];
        if (MODE == 2) {
            #pragma unroll
            for (int g = 0; g < 2; g++) {
                float h0, h1, h2, h3;
                unpack2(acc[o][2*g],   h0, h1);
                unpack2(acc[o][2*g+1], h2, h3);
                float pa = fmaxf(h0 + bv, 0.f) + fmaxf(h1 + bv, 0.f)
                         + fmaxf(h2 + bv, 0.f) + fmaxf(h3 + bv, 0.f);
                pa += __shfl_xor_sync(0xffffffffu, pa, 1);
                pa += __shfl_xor_sync(0xffffffffu, pa, 2);
                if ((lane & 3) == 0)
                    dst[og * TP + g * 8 + ptq] = pa;
            }
        } else {
            #pragma unroll
            for (int g = 0; g < 2; g++) {
                float h0, h1, h2, h3;
                unpack2(acc[o][2*g],   h0, h1);
                unpack2(acc[o][2*g+1], h2, h3);
                h0 = fmaxf(h0 + bv, 0.f);
                h1 = fmaxf(h1 + bv, 0.f);
                h2 = fmaxf(h2 + bv, 0.f);
                h3 = fmaxf(h3 + bv, 0.f);
                *(float4*)(dst + og * RR + g * 128 + lane * 4)
                    = make_float4(h0, h1, h2, h3);
            }
        }
    }
}

// ---------------------------------------------------------------------------
// Main kernel (unchanged except CTA offset), 3 CTAs/SM.
// ---------------------------------------------------------------------------
#define SMEM_FLOATS 17504

__global__ void __launch_bounds__(128, 3) main_kernel(
    const float* __restrict__ bb1, const float* __restrict__ bb2,
    float* __restrict__ out, int ofs)
{
    extern __shared__ float sm[];
    float* sb1 = sm;
    float* sb2 = sm + 32;
    float* red = sm + 96;
    float* XA  = sm + 1120;
    float* XB  = sm + 9312;

    const int tid  = threadIdx.x;
    const int base = (blockIdx.x + ofs) * TP;
    const int b    = base >> 12;
    const int p0   = base & (NP - 1);

    if (tid < 32)      sb1[tid] = bb1[tid];
    else if (tid < 96) { int o = tid - 32; sb2[o] = bb2[o] * (1.0f / 16.0f); }

    // ---- staging: h0 = relu(Y0s[q] + A[p]) into XB [o][r] ----
    {
        int r0s = tid * 2;
        int pt  = r0s >> 4;
        int k0  = r0s & 15;
        size_t rowp = (size_t)b * NP + (p0 + pt);
        int2 qq = *(const int2*)(g_idx + (rowp << 4) + k0);
        const ulonglong2* Ap  = (const ulonglong2*)(gA  + rowp * 32);
        const ulonglong2* Yq0 = (const ulonglong2*)(gY0 + ((size_t)b * NP + qq.x) * 32);
        const ulonglong2* Yq1 = (const ulonglong2*)(gY0 + ((size_t)b * NP + qq.y) * 32);
        #pragma unroll
        for (int jj = 0; jj < 8; jj++) {
            ulonglong2 av = Ap[jj];
            ulonglong2 y0 = Yq0[jj];
            ulonglong2 y1 = Yq1[jj];
            int o = jj * 4;
            {
                u64 c0 = add2(y0.x, av.x), c1 = add2(y1.x, av.x);
                float a0, b0_, a1, b1_;
                unpack2(c0, a0, b0_); unpack2(c1, a1, b1_);
                *(u64*)(XB + (o+0) * RR + r0s) = pack2(fmaxf(a0, 0.f), fmaxf(a1, 0.f));
                *(u64*)(XB + (o+1) * RR + r0s) = pack2(fmaxf(b0_, 0.f), fmaxf(b1_, 0.f));
            }
            {
                u64 c0 = add2(y0.y, av.y), c1 = add2(y1.y, av.y);
                float a0, b0_, a1, b1_;
                unpack2(c0, a0, b0_); unpack2(c1, a1, b1_);
                *(u64*)(XB + (o+2) * RR + r0s) = pack2(fmaxf(a0, 0.f), fmaxf(a1, 0.f));
                *(u64*)(XB + (o+3) * RR + r0s) = pack2(fmaxf(b0_, 0.f), fmaxf(b1_, 0.f));
            }
        }
    }
    __syncthreads();

    const int w_   = tid >> 5;
    const int lane = tid & 31;

    gemm_stage<1>(XB, XA, g_w1T, 32, w_ * 8, sb1, lane);
    __syncthreads();
    gemm_stage<2>(XA, red, g_w2T, 64, w_ * 8,      sb2, lane);
    gemm_stage<2>(XA, red, g_w2T, 64, 32 + w_ * 8, sb2, lane);
    __syncthreads();

    // ---- epilogue: out = relu(SC[p] + red) ----
    {
        int pt  = tid & 15;
        int o0s = (tid >> 4) * 8;
        const float4* scp = (const float4*)(gSC + ((size_t)b * NP + p0 + pt) * 64 + o0s);
        float4 s0 = scp[0], s1 = scp[1];
        float scv[8] = { s0.x, s0.y, s0.z, s0.w, s1.x, s1.y, s1.z, s1.w };
        #pragma unroll
        for (int j = 0; j < 8; j++) {
            int o = o0s + j;
            float v = scv[j] + red[o * TP + pt];
            out[((size_t)b * 64 + o) * NP + p0 + pt] = fmaxf(v, 0.f);
        }
    }
}

// ---------------------------------------------------------------------------
extern "C" void kernel_launch(void* const* d_in, const int* in_sizes, int n_in,
                              void* d_out, int out_size)
{
    (void)in_sizes; (void)n_in; (void)out_size;
    const float* features = (const float*)d_in[1];
    const int*   ef       = (const int*)d_in[2];

    static bool init_done = false;
    static cudaStream_t s1;
    static cudaEvent_t ev_fork, ev_edge, ev_wprep, ev_done;
    if (!init_done) {
        cudaFuncSetAttribute(main_kernel,
                             cudaFuncAttributeMaxDynamicSharedMemorySize,
                             SMEM_FLOATS * (int)sizeof(float));
        cudaFuncSetAttribute(pre_kernel,
                             cudaFuncAttributeMaxDynamicSharedMemorySize,
                             PRE_SMEM);
        cudaStreamCreateWithFlags(&s1, cudaStreamNonBlocking);
        cudaEventCreateWithFlags(&ev_fork,  cudaEventDisableTiming);
        cudaEventCreateWithFlags(&ev_edge,  cudaEventDisableTiming);
        cudaEventCreateWithFlags(&ev_wprep, cudaEventDisableTiming);
        cudaEventCreateWithFlags(&ev_done,  cudaEventDisableTiming);
        init_done = true;
    }

    const int HALF_MAIN = (BATCH * NP / TP) / 2;   // 2048 CTAs per half

    // fork
    cudaEventRecord(ev_fork, 0);
    cudaStreamWaitEvent(s1, ev_fork, 0);

    // stream1: edge pipeline, then preB + mainB (batches 8-15)
    prep_kernel<<<BATCH * 256, 256, 0, s1>>>(ef);
    {
        dim3 tg(EDG / 256, BATCH);
        scatter_kernel<<<tg, 256, 0, s1>>>(ef);
    }
    cudaEventRecord(ev_edge, s1);

    // stream0: weight prep, preA (batches 0-7)
    wprep_kernel<<<28, 256>>>((const float*)d_in[3], (const float*)d_in[6],
                              (const float*)d_in[9], (const float*)d_in[12],
                              (const float*)d_in[4], (const float*)d_in[13],
                              (const float*)d_in[7], (const float*)d_in[10]);
    cudaEventRecord(ev_wprep, 0);
    {
        dim3 tg(NP / PPB, BATCH / 2);   // (16, 8)
        pre_kernel<<<tg, 256, PRE_SMEM>>>(features, (const float*)d_in[5],
                                          (const float*)d_in[14], 0);
    }

    // stream1: preB (needs wprep) then mainB
    cudaStreamWaitEvent(s1, ev_wprep, 0);
    {
        dim3 tg(NP / PPB, BATCH / 2);
        pre_kernel<<<tg, 256, PRE_SMEM, s1>>>(features, (const float*)d_in[5],
                                              (const float*)d_in[14], BATCH / 2);
    }
    main_kernel<<<HALF_MAIN, 128, SMEM_FLOATS * sizeof(float), s1>>>(
        (const float*)d_in[8], (const float*)d_in[11],
        (float*)d_out, HALF_MAIN);
    cudaEventRecord(ev_done, s1);

    // stream0: mainA (needs preA in-order + edge)
    cudaStreamWaitEvent(0, ev_edge, 0);
    main_kernel<<<HALF_MAIN, 128, SMEM_FLOATS * sizeof(float)>>>(
        (const float*)d_in[8], (const float*)d_in[11],
        (float*)d_out, 0);

    // join
    cudaStreamWaitEvent(0, ev_done, 0);
}